// round 16
// baseline (speedup 1.0000x reference)
#include <cuda_runtime.h>
#include <cuda_bf16.h>
#include <cstdint>

#define N    2048
#define DIM  1024
#define DCLI 64

// ---- device scratch (no allocations allowed) ----
__device__ __nv_bfloat16 g_imh[N * DIM];   // hi(normalized phi_im)
__device__ __nv_bfloat16 g_iml[N * DIM];   // lo
__device__ __nv_bfloat16 g_clih[N * DCLI];
__device__ __nv_bfloat16 g_clil[N * DCLI];
__device__ int g_idx[3][N];                // compacted original indices per class
__device__ int g_cnt[3];                   // class sizes
__device__ unsigned long long g_minkey[6];

// monotone order-preserving float<->uint encoding (ascending)
__device__ __forceinline__ unsigned int enc_f(float f) {
    unsigned int b = __float_as_uint(f);
    return (b & 0x80000000u) ? ~b : (b | 0x80000000u);
}
__device__ __forceinline__ float dec_f(unsigned int e) {
    unsigned int b = (e & 0x80000000u) ? (e ^ 0x80000000u) : ~e;
    return __uint_as_float(b);
}
__device__ __forceinline__ unsigned long long ullmin2(unsigned long long a, unsigned long long b) {
    return a < b ? a : b;
}

// HMMA m16n8k16 bf16 -> f32 (base PTX, valid on sm_103 non-"a")
__device__ __forceinline__ void mma16816(float* d, const uint32_t* a, const uint32_t* b) {
    asm volatile("mma.sync.aligned.m16n8k16.row.col.f32.bf16.bf16.f32 "
                 "{%0,%1,%2,%3}, {%4,%5,%6,%7}, {%8,%9}, {%0,%1,%2,%3};"
                 : "+f"(d[0]), "+f"(d[1]), "+f"(d[2]), "+f"(d[3])
                 : "r"(a[0]), "r"(a[1]), "r"(a[2]), "r"(a[3]), "r"(b[0]), "r"(b[1]));
}
__device__ __forceinline__ void ldm_x4(uint32_t* r, uint32_t saddr) {
    asm volatile("ldmatrix.sync.aligned.m8n8.x4.shared.b16 {%0,%1,%2,%3}, [%4];"
                 : "=r"(r[0]), "=r"(r[1]), "=r"(r[2]), "=r"(r[3]) : "r"(saddr));
}
__device__ __forceinline__ uint32_t smem_u32(const void* p) {
    uint32_t a;
    asm("{ .reg .u64 t; cvta.to.shared.u64 t, %1; cvt.u32.u64 %0, t; }" : "=r"(a) : "l"(p));
    return a;
}
__device__ __forceinline__ void cp16(uint32_t dst, const void* src) {
    asm volatile("cp.async.cg.shared.global [%0], [%1], 16;" :: "r"(dst), "l"(src) : "memory");
}

// ---- row L2 normalization -> bf16 hi/lo split ----
__global__ void norm_im(const float* __restrict__ x) {
    int row = blockIdx.x;
    int t = threadIdx.x;                          // 256 threads, 4 floats each
    float4 a = ((const float4*)(x + (size_t)row * DIM))[t];
    float ss = a.x * a.x + a.y * a.y + a.z * a.z + a.w * a.w;
    #pragma unroll
    for (int o = 16; o; o >>= 1) ss += __shfl_xor_sync(0xffffffffu, ss, o);
    __shared__ float sred[8];
    if ((t & 31) == 0) sred[t >> 5] = ss;
    __syncthreads();
    __shared__ float stot;
    if (t == 0) {
        float s = 0.f;
        #pragma unroll
        for (int w = 0; w < 8; w++) s += sred[w];
        stot = s;
    }
    __syncthreads();
    float inv = 1.0f / fmaxf(sqrtf(stot), 1e-12f);
    float v[4] = {a.x * inv, a.y * inv, a.z * inv, a.w * inv};
    __nv_bfloat16 h[4], l[4];
    #pragma unroll
    for (int i = 0; i < 4; i++) {
        h[i] = __float2bfloat16(v[i]);
        l[i] = __float2bfloat16(v[i] - __bfloat162float(h[i]));
    }
    __nv_bfloat162* ph = (__nv_bfloat162*)(g_imh + (size_t)row * DIM);
    __nv_bfloat162* pl = (__nv_bfloat162*)(g_iml + (size_t)row * DIM);
    ph[2 * t]     = {h[0], h[1]};
    ph[2 * t + 1] = {h[2], h[3]};
    pl[2 * t]     = {l[0], l[1]};
    pl[2 * t + 1] = {l[2], l[3]};
}

__global__ void norm_cli(const float* __restrict__ x) {
    int row = blockIdx.x;
    int t = threadIdx.x;                          // 32 threads, 2 floats each
    float2 a = ((const float2*)(x + (size_t)row * DCLI))[t];
    float ss = a.x * a.x + a.y * a.y;
    #pragma unroll
    for (int o = 16; o; o >>= 1) ss += __shfl_xor_sync(0xffffffffu, ss, o);
    float inv = 1.0f / fmaxf(sqrtf(ss), 1e-12f);
    float v0 = a.x * inv, v1 = a.y * inv;
    __nv_bfloat16 h0 = __float2bfloat16(v0), h1 = __float2bfloat16(v1);
    __nv_bfloat16 l0 = __float2bfloat16(v0 - __bfloat162float(h0));
    __nv_bfloat16 l1 = __float2bfloat16(v1 - __bfloat162float(h1));
    ((__nv_bfloat162*)(g_clih + (size_t)row * DCLI))[t] = {h0, h1};
    ((__nv_bfloat162*)(g_clil + (size_t)row * DCLI))[t] = {l0, l1};
}

// ---- dtype detect + mask build + deterministic compaction (one block) ----
__global__ void build_sets(const int* __restrict__ t32, const int* __restrict__ tr32) {
    const int t = threadIdx.x;
    const int lane = t & 31, warp = t >> 5;
    __shared__ int wsum[3][8];
    __shared__ int base[3];

    int nz = 0;
    for (int w = 2 * t + 1; w < 2 * N; w += 2 * 256)
        nz |= (t32[w] != 0);
    nz = __syncthreads_or(nz);
    const int i32 = nz;

    if (t < 3) base[t] = 0;
    if (t < 6) g_minkey[t] = 0xFF80000000000000ull;  // enc(+inf)<<32 | 0
    __syncthreads();

    for (int chunk = 0; chunk < N; chunk += 256) {
        int i = chunk + t;
        int t1, tr;
        if (i32) { t1 = t32[2 * i + 1]; tr = tr32[i]; }
        else     { t1 = t32[4 * i + 2]; tr = tr32[2 * i]; }  // low words (vals 0..2)
        bool mem[3];
        mem[0] = (t1 == 0) && (tr == 1);
        mem[1] = (t1 == 1);
        mem[2] = (t1 == 2);

        int wpre[3];
        #pragma unroll
        for (int c = 0; c < 3; c++) {
            unsigned b = __ballot_sync(0xffffffffu, mem[c]);
            wpre[c] = __popc(b & ((1u << lane) - 1u));
            if (lane == 0) wsum[c][warp] = __popc(b);
        }
        __syncthreads();
        int ctot[3];
        #pragma unroll
        for (int c = 0; c < 3; c++) {
            int woff = 0;
            #pragma unroll
            for (int w = 0; w < 8; w++) if (w < warp) woff += wsum[c][w];
            int tot = 0;
            #pragma unroll
            for (int w = 0; w < 8; w++) tot += wsum[c][w];
            if (mem[c]) g_idx[c][base[c] + woff + wpre[c]] = i;
            ctot[c] = tot;
        }
        __syncthreads();
        if (t == 0) {
            #pragma unroll
            for (int c = 0; c < 3; c++) base[c] += ctot[c];
        }
        __syncthreads();
    }
    if (t < 3) g_cnt[t] = base[t];
}

// ---- HMMA bf16-split pair-GEMM + scatter + min/argmin ----
// grid (32,32,6): 64x64 tiles, 128 threads / 4 warps (each 32x32).
// 3-stage cp.async ring, one barrier per 32-K chunk. ~5 blocks/SM.
#define PITCH  40   // bf16 per smem row (32 data + 8 pad): conflict-free ldmatrix
#define STAGES 3
__global__ void __launch_bounds__(128, 5) pairgemm_mma(float* __restrict__ out) {
    __shared__ __nv_bfloat16 Asm[STAGES][64][PITCH];
    __shared__ __nv_bfloat16 Bsm[STAGES][64][PITCH];
    __shared__ int sA[64], sB[64];
    __shared__ unsigned long long smk[4];

    const int z = blockIdx.z, mod = z / 3, p = z % 3;
    const int pa[3] = {0, 0, 1};
    const int pb[3] = {1, 2, 2};
    const int ca = g_cnt[pa[p]], cb = g_cnt[pb[p]];
    const int i0 = blockIdx.y * 64, j0 = blockIdx.x * 64;
    if (i0 >= ca || j0 >= cb) return;

    const int tid = threadIdx.x, wid = tid >> 5, lid = tid & 31;
    const int wr = wid & 1, wc = wid >> 1;        // warp tile: rows wr*32, cols wc*32
    const int g = lid >> 2, tg = lid & 3;

    const int* __restrict__ idxA = g_idx[pa[p]];
    const int* __restrict__ idxB = g_idx[pb[p]];
    if (tid < 64)        sA[tid]      = idxA[min(i0 + tid, ca - 1)];
    else                 sB[tid - 64] = idxB[min(j0 + tid - 64, cb - 1)];
    __syncthreads();

    const __nv_bfloat16* __restrict__ Hi = mod ? g_clih : g_imh;
    const __nv_bfloat16* __restrict__ Lo = mod ? g_clil : g_iml;
    const int D  = mod ? DCLI : DIM;
    const int KC = D >> 5;               // 32-wide K chunks per pass
    const int C  = KC * 3;               // passes: hh, hl, lh

    // cp.async mapping: A/B each 256 segs of 8 bf16 (row=seg>>2, sc=seg&3), 2 segs/thread each
    const int r0s = tid >> 2,         sc0 = tid & 3;          // seg = tid        (rows 0..31)
    const int r1s = (tid + 128) >> 2, sc1 = tid & 3;          // seg = tid + 128  (rows 32..63)

    const uint32_t sbA = smem_u32(&Asm[0][0][0]);
    const uint32_t sbB = smem_u32(&Bsm[0][0][0]);

    // ldmatrix per-lane source coords (within tile)
    const int q = lid >> 3, rim = lid & 7;
    const int a_r = wr * 32 + (q & 1) * 8 + rim;      // + mt*16
    const int a_c = (q >> 1) * 8;                     // + ks*16
    const int b_r = wc * 32 + (q >> 1) * 8 + rim;     // + ntp*16
    const int b_c = (q & 1) * 8;                      // + ks*16

    float d[2][4][4];
    #pragma unroll
    for (int mt = 0; mt < 2; mt++)
        #pragma unroll
        for (int nt = 0; nt < 4; nt++)
            #pragma unroll
            for (int e = 0; e < 4; e++) d[mt][nt][e] = 0.f;

    // issue chunk s into stage s%STAGES (all async, per-thread)
    #define ISSUE(s) do {                                                             \
        const int _pass = (s) / KC, _k0 = ((s) % KC) * 32, _st = (s) % STAGES;        \
        const __nv_bfloat16* _As = (_pass == 2) ? Lo : Hi;                            \
        const __nv_bfloat16* _Bs = (_pass == 1) ? Lo : Hi;                            \
        const uint32_t _da = sbA + (uint32_t)_st * 64 * PITCH * 2;                    \
        const uint32_t _db = sbB + (uint32_t)_st * 64 * PITCH * 2;                    \
        cp16(_da + (uint32_t)(r0s * PITCH + sc0 * 8) * 2,                             \
             _As + (size_t)sA[r0s] * D + _k0 + sc0 * 8);                              \
        cp16(_da + (uint32_t)(r1s * PITCH + sc1 * 8) * 2,                             \
             _As + (size_t)sA[r1s] * D + _k0 + sc1 * 8);                              \
        cp16(_db + (uint32_t)(r0s * PITCH + sc0 * 8) * 2,                             \
             _Bs + (size_t)sB[r0s] * D + _k0 + sc0 * 8);                              \
        cp16(_db + (uint32_t)(r1s * PITCH + sc1 * 8) * 2,                             \
             _Bs + (size_t)sB[r1s] * D + _k0 + sc1 * 8);                              \
        asm volatile("cp.async.commit_group;" ::: "memory");                          \
    } while (0)

    ISSUE(0);
    ISSUE(1);

    for (int s = 0; s < C; s++) {
        asm volatile("cp.async.wait_group 1;" ::: "memory");   // chunk s landed
        __syncthreads();                                        // + all warps done with chunk s-1
        if (s + 2 < C) ISSUE(s + 2);
        else asm volatile("cp.async.commit_group;" ::: "memory");  // keep group count uniform

        const int st = s % STAGES;
        const uint32_t baseA = sbA + (uint32_t)st * 64 * PITCH * 2;
        const uint32_t baseB = sbB + (uint32_t)st * 64 * PITCH * 2;
        #pragma unroll
        for (int ks = 0; ks < 2; ks++) {      // two k16 steps per 32-chunk
            uint32_t af[2][4], bf[4][2];
            #pragma unroll
            for (int mt = 0; mt < 2; mt++)
                ldm_x4(af[mt], baseA + ((a_r + mt * 16) * PITCH + ks * 16 + a_c) * 2);
            #pragma unroll
            for (int ntp = 0; ntp < 2; ntp++) {
                uint32_t rr[4];
                ldm_x4(rr, baseB + ((b_r + ntp * 16) * PITCH + ks * 16 + b_c) * 2);
                bf[ntp * 2][0] = rr[0]; bf[ntp * 2][1] = rr[1];
                bf[ntp * 2 + 1][0] = rr[2]; bf[ntp * 2 + 1][1] = rr[3];
            }
            #pragma unroll
            for (int mt = 0; mt < 2; mt++)
                #pragma unroll
                for (int nt = 0; nt < 4; nt++)
                    mma16816(d[mt][nt], af[mt], bf[nt]);
        }
    }

    // epilogue: scatter from register fragments + min-key
    float* __restrict__ po = out + (size_t)(mod * 3 + p) * N * N;
    unsigned long long mk = 0xFFFFFFFFFFFFFFFFull;
    #pragma unroll
    for (int mt = 0; mt < 2; mt++) {
        int r0 = wr * 32 + mt * 16 + g;
        int r1 = r0 + 8;
        int gi0 = (i0 + r0 < ca) ? sA[r0] : -1;
        int gi1 = (i0 + r1 < ca) ? sA[r1] : -1;
        #pragma unroll
        for (int nt = 0; nt < 4; nt++) {
            int c0 = wc * 32 + nt * 8 + tg * 2;
            int gj0 = (j0 + c0 < cb) ? sB[c0] : -1;
            int gj1 = (j0 + c0 + 1 < cb) ? sB[c0 + 1] : -1;
            float* v = d[mt][nt];
            if (gi0 >= 0 && gj0 >= 0) {
                unsigned int off = (unsigned int)(gi0 * N + gj0);
                po[off] = v[0];
                mk = ullmin2(mk, ((unsigned long long)enc_f(v[0]) << 32) | off);
            }
            if (gi0 >= 0 && gj1 >= 0) {
                unsigned int off = (unsigned int)(gi0 * N + gj1);
                po[off] = v[1];
                mk = ullmin2(mk, ((unsigned long long)enc_f(v[1]) << 32) | off);
            }
            if (gi1 >= 0 && gj0 >= 0) {
                unsigned int off = (unsigned int)(gi1 * N + gj0);
                po[off] = v[2];
                mk = ullmin2(mk, ((unsigned long long)enc_f(v[2]) << 32) | off);
            }
            if (gi1 >= 0 && gj1 >= 0) {
                unsigned int off = (unsigned int)(gi1 * N + gj1);
                po[off] = v[3];
                mk = ullmin2(mk, ((unsigned long long)enc_f(v[3]) << 32) | off);
            }
        }
    }
    #pragma unroll
    for (int o = 16; o; o >>= 1)
        mk = ullmin2(mk, __shfl_xor_sync(0xffffffffu, mk, o));
    if (lid == 0) smk[wid] = mk;
    __syncthreads();
    if (tid == 0) {
        unsigned long long r = smk[0];
        #pragma unroll
        for (int w = 1; w < 4; w++) r = ullmin2(r, smk[w]);
        atomicMin(&g_minkey[mod * 3 + p], r);
    }
}

// ---- finalize: decode keys into min_vals + min_idx (bounds-guarded) ----
__global__ void finalize(float* __restrict__ out, long long out_elems) {
    int i = threadIdx.x;
    if (i < 6) {
        unsigned long long k = g_minkey[i];
        float v = dec_f((unsigned int)(k >> 32));
        unsigned int flat = (unsigned int)(k & 0xFFFFFFFFull);
        long long base = (long long)6 * N * N;
        if (base + i < out_elems)
            out[base + i] = v;
        if (base + 6 + 2 * i + 1 < out_elems) {
            out[base + 6 + 2 * i]     = (float)(flat / N);
            out[base + 6 + 2 * i + 1] = (float)(flat % N);
        }
    }
}

extern "C" void kernel_launch(void* const* d_in, const int* in_sizes, int n_in,
                              void* d_out, int out_size) {
    const float* phi_im  = (const float*)d_in[0];
    const float* phi_cli = (const float*)d_in[1];
    const int*   t32     = (const int*)d_in[2];
    const int*   tr32    = (const int*)d_in[3];
    float* out = (float*)d_out;

    // background zeros for all 6 masked matrices (capturable memset node)
    cudaMemsetAsync(d_out, 0, (size_t)out_size * sizeof(float), 0);

    norm_im<<<N, 256>>>(phi_im);
    norm_cli<<<N, 32>>>(phi_cli);
    build_sets<<<1, 256>>>(t32, tr32);

    pairgemm_mma<<<dim3(32, 32, 6), 128>>>(out);
    finalize<<<1, 32>>>(out, (long long)out_size);
}

// round 17
// speedup vs baseline: 1.2954x; 1.2954x over previous
#include <cuda_runtime.h>
#include <cuda_bf16.h>
#include <cstdint>

#define N    2048
#define DIM  1024
#define DCLI 64
#define TCAP 288    // >= max 64x64 tiles per pair: (a/64)*(b/64) <= 256 for a+b<=2048

// ---- device scratch (no allocations allowed) ----
__device__ __nv_bfloat16 g_imh[N * DIM];   // hi(normalized phi_im)
__device__ __nv_bfloat16 g_iml[N * DIM];   // lo
__device__ __nv_bfloat16 g_clih[N * DCLI];
__device__ __nv_bfloat16 g_clil[N * DCLI];
__device__ int g_idx[3][N];                // compacted original indices per class
__device__ int g_cnt[3];                   // class sizes
__device__ unsigned long long g_minkey[6];
__device__ float g_part[3 * 2 * TCAP * 4096];   // mod0 split-K partials (28.3 MB)

// monotone order-preserving float<->uint encoding (ascending)
__device__ __forceinline__ unsigned int enc_f(float f) {
    unsigned int b = __float_as_uint(f);
    return (b & 0x80000000u) ? ~b : (b | 0x80000000u);
}
__device__ __forceinline__ float dec_f(unsigned int e) {
    unsigned int b = (e & 0x80000000u) ? (e ^ 0x80000000u) : ~e;
    return __uint_as_float(b);
}
__device__ __forceinline__ unsigned long long ullmin2(unsigned long long a, unsigned long long b) {
    return a < b ? a : b;
}

// HMMA m16n8k16 bf16 -> f32 (base PTX, valid on sm_103 non-"a")
__device__ __forceinline__ void mma16816(float* d, const uint32_t* a, const uint32_t* b) {
    asm volatile("mma.sync.aligned.m16n8k16.row.col.f32.bf16.bf16.f32 "
                 "{%0,%1,%2,%3}, {%4,%5,%6,%7}, {%8,%9}, {%0,%1,%2,%3};"
                 : "+f"(d[0]), "+f"(d[1]), "+f"(d[2]), "+f"(d[3])
                 : "r"(a[0]), "r"(a[1]), "r"(a[2]), "r"(a[3]), "r"(b[0]), "r"(b[1]));
}
__device__ __forceinline__ void ldm_x4(uint32_t* r, uint32_t saddr) {
    asm volatile("ldmatrix.sync.aligned.m8n8.x4.shared.b16 {%0,%1,%2,%3}, [%4];"
                 : "=r"(r[0]), "=r"(r[1]), "=r"(r[2]), "=r"(r[3]) : "r"(saddr));
}
__device__ __forceinline__ uint32_t smem_u32(const void* p) {
    uint32_t a;
    asm("{ .reg .u64 t; cvta.to.shared.u64 t, %1; cvt.u32.u64 %0, t; }" : "=r"(a) : "l"(p));
    return a;
}
__device__ __forceinline__ void cp16(uint32_t dst, const void* src) {
    asm volatile("cp.async.cg.shared.global [%0], [%1], 16;" :: "r"(dst), "l"(src) : "memory");
}

// ---- row L2 normalization -> bf16 hi/lo split ----
__global__ void norm_im(const float* __restrict__ x) {
    int row = blockIdx.x;
    int t = threadIdx.x;                          // 256 threads, 4 floats each
    float4 a = ((const float4*)(x + (size_t)row * DIM))[t];
    float ss = a.x * a.x + a.y * a.y + a.z * a.z + a.w * a.w;
    #pragma unroll
    for (int o = 16; o; o >>= 1) ss += __shfl_xor_sync(0xffffffffu, ss, o);
    __shared__ float sred[8];
    if ((t & 31) == 0) sred[t >> 5] = ss;
    __syncthreads();
    __shared__ float stot;
    if (t == 0) {
        float s = 0.f;
        #pragma unroll
        for (int w = 0; w < 8; w++) s += sred[w];
        stot = s;
    }
    __syncthreads();
    float inv = 1.0f / fmaxf(sqrtf(stot), 1e-12f);
    float v[4] = {a.x * inv, a.y * inv, a.z * inv, a.w * inv};
    __nv_bfloat16 h[4], l[4];
    #pragma unroll
    for (int i = 0; i < 4; i++) {
        h[i] = __float2bfloat16(v[i]);
        l[i] = __float2bfloat16(v[i] - __bfloat162float(h[i]));
    }
    __nv_bfloat162* ph = (__nv_bfloat162*)(g_imh + (size_t)row * DIM);
    __nv_bfloat162* pl = (__nv_bfloat162*)(g_iml + (size_t)row * DIM);
    ph[2 * t]     = {h[0], h[1]};
    ph[2 * t + 1] = {h[2], h[3]};
    pl[2 * t]     = {l[0], l[1]};
    pl[2 * t + 1] = {l[2], l[3]};
}

__global__ void norm_cli(const float* __restrict__ x) {
    int row = blockIdx.x;
    int t = threadIdx.x;                          // 32 threads, 2 floats each
    float2 a = ((const float2*)(x + (size_t)row * DCLI))[t];
    float ss = a.x * a.x + a.y * a.y;
    #pragma unroll
    for (int o = 16; o; o >>= 1) ss += __shfl_xor_sync(0xffffffffu, ss, o);
    float inv = 1.0f / fmaxf(sqrtf(ss), 1e-12f);
    float v0 = a.x * inv, v1 = a.y * inv;
    __nv_bfloat16 h0 = __float2bfloat16(v0), h1 = __float2bfloat16(v1);
    __nv_bfloat16 l0 = __float2bfloat16(v0 - __bfloat162float(h0));
    __nv_bfloat16 l1 = __float2bfloat16(v1 - __bfloat162float(h1));
    ((__nv_bfloat162*)(g_clih + (size_t)row * DCLI))[t] = {h0, h1};
    ((__nv_bfloat162*)(g_clil + (size_t)row * DCLI))[t] = {l0, l1};
}

// ---- dtype detect + mask build + deterministic compaction (one block) ----
__global__ void build_sets(const int* __restrict__ t32, const int* __restrict__ tr32) {
    const int t = threadIdx.x;
    const int lane = t & 31, warp = t >> 5;
    __shared__ int wsum[3][8];
    __shared__ int base[3];

    int nz = 0;
    for (int w = 2 * t + 1; w < 2 * N; w += 2 * 256)
        nz |= (t32[w] != 0);
    nz = __syncthreads_or(nz);
    const int i32 = nz;

    if (t < 3) base[t] = 0;
    if (t < 6) g_minkey[t] = 0xFF80000000000000ull;  // enc(+inf)<<32 | 0
    __syncthreads();

    for (int chunk = 0; chunk < N; chunk += 256) {
        int i = chunk + t;
        int t1, tr;
        if (i32) { t1 = t32[2 * i + 1]; tr = tr32[i]; }
        else     { t1 = t32[4 * i + 2]; tr = tr32[2 * i]; }  // low words (vals 0..2)
        bool mem[3];
        mem[0] = (t1 == 0) && (tr == 1);
        mem[1] = (t1 == 1);
        mem[2] = (t1 == 2);

        int wpre[3];
        #pragma unroll
        for (int c = 0; c < 3; c++) {
            unsigned b = __ballot_sync(0xffffffffu, mem[c]);
            wpre[c] = __popc(b & ((1u << lane) - 1u));
            if (lane == 0) wsum[c][warp] = __popc(b);
        }
        __syncthreads();
        int ctot[3];
        #pragma unroll
        for (int c = 0; c < 3; c++) {
            int woff = 0;
            #pragma unroll
            for (int w = 0; w < 8; w++) if (w < warp) woff += wsum[c][w];
            int tot = 0;
            #pragma unroll
            for (int w = 0; w < 8; w++) tot += wsum[c][w];
            if (mem[c]) g_idx[c][base[c] + woff + wpre[c]] = i;
            ctot[c] = tot;
        }
        __syncthreads();
        if (t == 0) {
            #pragma unroll
            for (int c = 0; c < 3; c++) base[c] += ctot[c];
        }
        __syncthreads();
    }
    if (t < 3) g_cnt[t] = base[t];
}

// ---- HMMA bf16-split pair-GEMM: 64x64 tiles, 4 warps, K-chunks of 64, 2-stage ----
// grid (32,32,9): z<6 -> mod0 (pair=z>>1, split=z&1, K half of 512) -> partials;
//                 z>=6 -> mod1 (D=64) direct scatter epilogue.
#define PITCH 72    // bf16 per smem row (64 data + 8 pad): 36-word stride, conflict-free
__global__ void __launch_bounds__(128, 5) pairgemm_mma(float* __restrict__ out) {
    __shared__ __nv_bfloat16 Asm[2][64][PITCH];
    __shared__ __nv_bfloat16 Bsm[2][64][PITCH];
    __shared__ int sA[64], sB[64];
    __shared__ unsigned long long smk[4];

    const int z = blockIdx.z;
    const int mod   = (z < 6) ? 0 : 1;
    const int p     = (z < 6) ? (z >> 1) : (z - 6);
    const int split = (z < 6) ? (z & 1) : 0;
    const int pa[3] = {0, 0, 1};
    const int pb[3] = {1, 2, 2};
    const int ca = g_cnt[pa[p]], cb = g_cnt[pb[p]];
    const int i0 = blockIdx.y * 64, j0 = blockIdx.x * 64;
    if (i0 >= ca || j0 >= cb) return;

    const int tid = threadIdx.x, wid = tid >> 5, lid = tid & 31;
    const int wr = wid & 1, wc = wid >> 1;        // warp tile: rows wr*32, cols wc*32
    const int g = lid >> 2, tg = lid & 3;

    const int* __restrict__ idxA = g_idx[pa[p]];
    const int* __restrict__ idxB = g_idx[pb[p]];
    if (tid < 64)        sA[tid]      = idxA[min(i0 + tid, ca - 1)];
    else                 sB[tid - 64] = idxB[min(j0 + tid - 64, cb - 1)];
    __syncthreads();

    const __nv_bfloat16* __restrict__ Hi = mod ? g_clih : g_imh;
    const __nv_bfloat16* __restrict__ Lo = mod ? g_clil : g_iml;
    const int D    = mod ? DCLI : DIM;
    const int kbeg = mod ? 0 : split * 512;
    const int KCp  = mod ? 1 : 8;        // 64-wide chunks per pass
    const int C    = KCp * 3;            // passes: hh, hl, lh

    // cp.async mapping: tile = 512 segs of 16B; 4 segs/thread: seg = tid + q*128
    const uint32_t sbA = smem_u32(&Asm[0][0][0]);
    const uint32_t sbB = smem_u32(&Bsm[0][0][0]);

    // ldmatrix per-lane source coords (within tile)
    const int q = lid >> 3, rim = lid & 7;
    const int a_r = wr * 32 + (q & 1) * 8 + rim;      // + mt*16
    const int a_c = (q >> 1) * 8;                     // + ks*16
    const int b_r = wc * 32 + (q >> 1) * 8 + rim;     // + ntp*16
    const int b_c = (q & 1) * 8;                      // + ks*16

    float d[2][4][4];
    #pragma unroll
    for (int mt = 0; mt < 2; mt++)
        #pragma unroll
        for (int nt = 0; nt < 4; nt++)
            #pragma unroll
            for (int e = 0; e < 4; e++) d[mt][nt][e] = 0.f;

    // issue 64-wide chunk s into stage s&1
    #define ISSUE(s) do {                                                             \
        const int _pass = (s) / KCp, _k0 = kbeg + ((s) % KCp) * 64, _st = (s) & 1;    \
        const __nv_bfloat16* _As = (_pass == 2) ? Lo : Hi;                            \
        const __nv_bfloat16* _Bs = (_pass == 1) ? Lo : Hi;                            \
        const uint32_t _da = sbA + (uint32_t)_st * 64 * PITCH * 2;                    \
        const uint32_t _db = sbB + (uint32_t)_st * 64 * PITCH * 2;                    \
        _Pragma("unroll")                                                             \
        for (int _q = 0; _q < 4; _q++) {                                              \
            int _seg = tid + _q * 128;                                                \
            int _row = _seg >> 3, _sc = _seg & 7;                                     \
            cp16(_da + (uint32_t)(_row * PITCH + _sc * 8) * 2,                        \
                 _As + (size_t)sA[_row] * D + _k0 + _sc * 8);                         \
            cp16(_db + (uint32_t)(_row * PITCH + _sc * 8) * 2,                        \
                 _Bs + (size_t)sB[_row] * D + _k0 + _sc * 8);                         \
        }                                                                             \
        asm volatile("cp.async.commit_group;" ::: "memory");                          \
    } while (0)

    ISSUE(0);

    for (int s = 0; s < C; s++) {
        if (s + 1 < C) {
            ISSUE(s + 1);
            asm volatile("cp.async.wait_group 1;" ::: "memory");
        } else {
            asm volatile("cp.async.wait_group 0;" ::: "memory");
        }
        __syncthreads();                       // chunk s visible to all warps

        const int st = s & 1;
        const uint32_t baseA = sbA + (uint32_t)st * 64 * PITCH * 2;
        const uint32_t baseB = sbB + (uint32_t)st * 64 * PITCH * 2;
        #pragma unroll
        for (int ks = 0; ks < 4; ks++) {       // four k16 steps per 64-chunk
            uint32_t af[2][4], bf[4][2];
            #pragma unroll
            for (int mt = 0; mt < 2; mt++)
                ldm_x4(af[mt], baseA + ((a_r + mt * 16) * PITCH + ks * 16 + a_c) * 2);
            #pragma unroll
            for (int ntp = 0; ntp < 2; ntp++) {
                uint32_t rr[4];
                ldm_x4(rr, baseB + ((b_r + ntp * 16) * PITCH + ks * 16 + b_c) * 2);
                bf[ntp * 2][0] = rr[0]; bf[ntp * 2][1] = rr[1];
                bf[ntp * 2 + 1][0] = rr[2]; bf[ntp * 2 + 1][1] = rr[3];
            }
            #pragma unroll
            for (int mt = 0; mt < 2; mt++)
                #pragma unroll
                for (int nt = 0; nt < 4; nt++)
                    mma16816(d[mt][nt], af[mt], bf[nt]);
        }
        __syncthreads();                       // protect stage before re-issue
    }

    if (mod == 0) {
        // write 64x64 partial tile (tile-linear f32) to scratch
        const int ntx = (cb + 63) >> 6;
        float* pp = g_part +
            ((size_t)(p * 2 + split) * TCAP + (size_t)blockIdx.y * ntx + blockIdx.x) * 4096;
        #pragma unroll
        for (int mt = 0; mt < 2; mt++) {
            int r0 = wr * 32 + mt * 16 + g;
            #pragma unroll
            for (int nt = 0; nt < 4; nt++) {
                int c0 = wc * 32 + nt * 8 + tg * 2;
                float* v = d[mt][nt];
                *(float2*)(pp + r0 * 64 + c0)       = make_float2(v[0], v[1]);
                *(float2*)(pp + (r0 + 8) * 64 + c0) = make_float2(v[2], v[3]);
            }
        }
        return;
    }

    // mod1: direct scatter + min epilogue
    float* __restrict__ po = out + (size_t)(3 + p) * N * N;
    unsigned long long mk = 0xFFFFFFFFFFFFFFFFull;
    #pragma unroll
    for (int mt = 0; mt < 2; mt++) {
        int r0 = wr * 32 + mt * 16 + g;
        int r1 = r0 + 8;
        int gi0 = (i0 + r0 < ca) ? sA[r0] : -1;
        int gi1 = (i0 + r1 < ca) ? sA[r1] : -1;
        #pragma unroll
        for (int nt = 0; nt < 4; nt++) {
            int c0 = wc * 32 + nt * 8 + tg * 2;
            int gj0 = (j0 + c0 < cb) ? sB[c0] : -1;
            int gj1 = (j0 + c0 + 1 < cb) ? sB[c0 + 1] : -1;
            float* v = d[mt][nt];
            if (gi0 >= 0 && gj0 >= 0) {
                unsigned int off = (unsigned int)(gi0 * N + gj0);
                po[off] = v[0];
                mk = ullmin2(mk, ((unsigned long long)enc_f(v[0]) << 32) | off);
            }
            if (gi0 >= 0 && gj1 >= 0) {
                unsigned int off = (unsigned int)(gi0 * N + gj1);
                po[off] = v[1];
                mk = ullmin2(mk, ((unsigned long long)enc_f(v[1]) << 32) | off);
            }
            if (gi1 >= 0 && gj0 >= 0) {
                unsigned int off = (unsigned int)(gi1 * N + gj0);
                po[off] = v[2];
                mk = ullmin2(mk, ((unsigned long long)enc_f(v[2]) << 32) | off);
            }
            if (gi1 >= 0 && gj1 >= 0) {
                unsigned int off = (unsigned int)(gi1 * N + gj1);
                po[off] = v[3];
                mk = ullmin2(mk, ((unsigned long long)enc_f(v[3]) << 32) | off);
            }
        }
    }
    #pragma unroll
    for (int o = 16; o; o >>= 1)
        mk = ullmin2(mk, __shfl_xor_sync(0xffffffffu, mk, o));
    if (lid == 0) smk[wid] = mk;
    __syncthreads();
    if (tid == 0) {
        unsigned long long r = smk[0];
        #pragma unroll
        for (int w = 1; w < 4; w++) r = ullmin2(r, smk[w]);
        atomicMin(&g_minkey[3 + p], r);
    }
}

// ---- combine mod0 split-K partials: fixed-order sum + scatter + min ----
__global__ void __launch_bounds__(128) combine(float* __restrict__ out) {
    const int p = blockIdx.z;
    const int pa[3] = {0, 0, 1};
    const int pb[3] = {1, 2, 2};
    const int ca = g_cnt[pa[p]], cb = g_cnt[pb[p]];
    const int i0 = blockIdx.y * 64, j0 = blockIdx.x * 64;
    if (i0 >= ca || j0 >= cb) return;

    const int ntx = (cb + 63) >> 6;
    const size_t slot = (size_t)blockIdx.y * ntx + blockIdx.x;
    const float4* P0 = (const float4*)(g_part + ((size_t)(p * 2 + 0) * TCAP + slot) * 4096);
    const float4* P1 = (const float4*)(g_part + ((size_t)(p * 2 + 1) * TCAP + slot) * 4096);

    const int* __restrict__ idxA = g_idx[pa[p]];
    const int* __restrict__ idxB = g_idx[pb[p]];
    float* __restrict__ po = out + (size_t)p * N * N;

    __shared__ unsigned long long smk[4];
    const int t = threadIdx.x;
    unsigned long long mk = 0xFFFFFFFFFFFFFFFFull;

    #pragma unroll
    for (int r = 0; r < 8; r++) {
        int f4 = t + r * 128;                 // 0..1023 float4 within 64x64 tile
        float4 v = P0[f4];
        float4 b1 = P1[f4]; v.x += b1.x; v.y += b1.y; v.z += b1.z; v.w += b1.w;
        int e = f4 * 4;
        int row = e >> 6, col = e & 63;
        if (i0 + row >= ca) continue;
        int gi = idxA[i0 + row];
        float vv[4] = {v.x, v.y, v.z, v.w};
        #pragma unroll
        for (int c = 0; c < 4; c++) {
            int jj = j0 + col + c;
            if (jj >= cb) continue;
            unsigned int off = (unsigned int)(gi * N + idxB[jj]);
            po[off] = vv[c];
            mk = ullmin2(mk, ((unsigned long long)enc_f(vv[c]) << 32) | off);
        }
    }

    #pragma unroll
    for (int o = 16; o; o >>= 1)
        mk = ullmin2(mk, __shfl_xor_sync(0xffffffffu, mk, o));
    if ((t & 31) == 0) smk[t >> 5] = mk;
    __syncthreads();
    if (t == 0) {
        unsigned long long r = smk[0];
        #pragma unroll
        for (int w = 1; w < 4; w++) r = ullmin2(r, smk[w]);
        atomicMin(&g_minkey[p], r);
    }
}

// ---- finalize: decode keys into min_vals + min_idx (bounds-guarded) ----
__global__ void finalize(float* __restrict__ out, long long out_elems) {
    int i = threadIdx.x;
    if (i < 6) {
        unsigned long long k = g_minkey[i];
        float v = dec_f((unsigned int)(k >> 32));
        unsigned int flat = (unsigned int)(k & 0xFFFFFFFFull);
        long long base = (long long)6 * N * N;
        if (base + i < out_elems)
            out[base + i] = v;
        if (base + 6 + 2 * i + 1 < out_elems) {
            out[base + 6 + 2 * i]     = (float)(flat / N);
            out[base + 6 + 2 * i + 1] = (float)(flat % N);
        }
    }
}

extern "C" void kernel_launch(void* const* d_in, const int* in_sizes, int n_in,
                              void* d_out, int out_size) {
    const float* phi_im  = (const float*)d_in[0];
    const float* phi_cli = (const float*)d_in[1];
    const int*   t32     = (const int*)d_in[2];
    const int*   tr32    = (const int*)d_in[3];
    float* out = (float*)d_out;

    // background zeros for all 6 masked matrices (capturable memset node)
    cudaMemsetAsync(d_out, 0, (size_t)out_size * sizeof(float), 0);

    norm_im<<<N, 256>>>(phi_im);
    norm_cli<<<N, 32>>>(phi_cli);
    build_sets<<<1, 256>>>(t32, tr32);

    pairgemm_mma<<<dim3(32, 32, 9), 128>>>(out);
    combine<<<dim3(32, 32, 3), 128>>>(out);
    finalize<<<1, 32>>>(out, (long long)out_size);
}